// round 4
// baseline (speedup 1.0000x reference)
#include <cuda_runtime.h>
#include <math.h>

// Problem constants (fixed shapes)
#define NB 4
#define HB 512
#define WB 512
#define NPIX (NB * HB * WB)   // 1,048,576 pixels

#define SIGMA_F 1e-4f
#define GAMMA_F 1e-4f
// DELTA = exp(1e-10/1e-4)*1e-10 computed in float64 -> float32
#define DELTA_F 1.0000010000005e-10f

// Accumulator: per (n, y, x) -> {sum r*w, sum g*w, sum b*w, sum w} (16 MB)
__device__ float4 g_accum[NB * HB * WB];

__global__ __launch_bounds__(256) void splat_kernel(
    const int*   __restrict__ p2f,     // [N,H,W,K]
    const float* __restrict__ bary,    // [N,H,W,K,3]
    const float* __restrict__ dists,   // [N,H,W,K]
    const float* __restrict__ zbuf,    // [N,H,W,K]
    const float* __restrict__ images,  // [N,H,W,C]
    const float* __restrict__ fuv)     // [F,3,2]
{
    int idx = blockIdx.x * blockDim.x + threadIdx.x;
    if (idx >= NPIX) return;
    int w = idx & (WB - 1);
    int h = (idx >> 9) & (HB - 1);
    int n = idx >> 18;

    // Vector loads only for tensors needed at full K (mask + z-max).
    int4   f4 = __ldg(((const int4*)p2f) + idx);
    float4 z4 = __ldg(((const float4*)zbuf) + idx);
    float r = __ldg(images + (size_t)idx * 3 + 0);
    float g = __ldg(images + (size_t)idx * 3 + 1);
    float b = __ldg(images + (size_t)idx * 3 + 2);

    int   fk[4] = {f4.x, f4.y, f4.z, f4.w};
    float zk[4] = {z4.x, z4.y, z4.z, z4.w};

    // ---- Candidate selection on CHEAP approximate z_inv ----
    // exp((z_inv - z_max)/GAMMA) is bitwise 0 whenever z_inv - z_max <
    // -0.0105 (arg < -104.9 < log(min_subnormal/2)). Approximate z_inv errs
    // <= ~2.4e-7 << window slack, so candidates provably cover all nonzero
    // exps; excluded k have wnum == 0 exactly.
    const float R99 = 1.0f / 99.0f;
    float zA[4];
    bool  m[4];
    float maxA = -1e30f;
    #pragma unroll
    for (int k = 0; k < 4; k++) {
        m[k] = (fk[k] >= 0);
        zA[k] = m[k] ? (100.0f - zk[k]) * R99 : 0.0f;
        maxA = fmaxf(maxA, zA[k]);
    }
    float thresh = maxA - 0.0105f;

    // Exact z_inv (true division; rounding is amplified x1e4 by the exp)
    // for candidates only; exact z_max over candidates == exact global max.
    bool  cand[4];
    float ze[4];
    float zmax = -1e30f;
    #pragma unroll
    for (int k = 0; k < 4; k++) {
        cand[k] = m[k] && (zA[k] >= thresh);
        ze[k] = cand[k] ? __fdiv_rn(__fsub_rn(100.0f, zk[k]), 99.0f) : -1e30f;
        zmax = fmaxf(zmax, ze[k]);
    }

    // wnum: heavy path (exp/sigmoid + lazy dists load) only where nonzero.
    float wnum[4];
    float s = 0.0f;
    #pragma unroll
    for (int k = 0; k < 4; k++) {
        float wv = 0.0f;
        if (cand[k]) {
            float earg = __fdiv_rn(__fsub_rn(ze[k], zmax), GAMMA_F);
            float e = expf(earg);          // argmax: earg==0 -> e==1 exactly
            if (e != 0.0f) {
                float dkk = __ldg(dists + (size_t)idx * 4 + k);
                float sarg = __fdiv_rn(-dkk, SIGMA_F);
                float pr = __fdiv_rn(1.0f, __fadd_rn(1.0f, expf(-sarg)));
                wv = __fmul_rn(pr, e);
            }
        }
        wnum[k] = wv;
        s = __fadd_rn(s, wv);
    }
    float denom = __fadd_rn(s, DELTA_F);

    // linspace(0, 512, 512)[i] = i * (512/511)
    const float STEP = 512.0f / 511.0f;
    float linx = __fmul_rn((float)w, STEP);
    float liny = __fmul_rn((float)h, STEP);

    float4* accum_n = g_accum + ((size_t)n << 18);

    #pragma unroll
    for (int k = 0; k < 4; k++) {
        if (wnum[k] == 0.0f) continue;   // scatter of zeros == bitwise no-op
        float wt = __fdiv_rn(wnum[k], denom);

        // Lazy barycentric load (12B of the 48B/pixel actually needed).
        const float* bp = bary + (size_t)idx * 12 + k * 3;
        float b0 = __ldg(bp + 0);
        float b1 = __ldg(bp + 1);
        float b2 = __ldg(bp + 2);

        // Gather face UVs and blend. Strict mul/add (no FMA) to match XLA:
        // the floor() bin below is last-ulp sensitive.
        const float* uvp = fuv + (size_t)fk[k] * 6;
        float ux = __fadd_rn(__fadd_rn(__fmul_rn(b0, __ldg(uvp + 0)),
                                       __fmul_rn(b1, __ldg(uvp + 2))),
                             __fmul_rn(b2, __ldg(uvp + 4)));
        float uy = __fadd_rn(__fadd_rn(__fmul_rn(b0, __ldg(uvp + 1)),
                                       __fmul_rn(b1, __ldg(uvp + 3))),
                             __fmul_rn(b2, __ldg(uvp + 5)));

        float gx = __fadd_rn(__fmul_rn(ux, 2.0f), -1.0f);
        float gy = __fadd_rn(__fmul_rn(uy, 2.0f), -1.0f);
        float tgx = __fmul_rn(__fadd_rn(__fmul_rn(gx, 0.5f), 0.5f), 512.0f);
        float tgy = __fmul_rn(__fadd_rn(__fmul_rn(gy, 0.5f), 0.5f), 512.0f);

        float fx = __fadd_rn(__fsub_rn(tgx, linx), (float)w);
        float fy = __fadd_rn(__fsub_rn(tgy, liny), (float)h);

        float x0f = floorf(fx), y0f = floorf(fy);
        int x0 = (int)x0f, y0 = (int)y0f;
        float tx = __fsub_rn(fx, x0f), ty = __fsub_rn(fy, y0f);

        float vr = __fmul_rn(r, wt), vg = __fmul_rn(g, wt), vb = __fmul_rn(b, wt);

        #pragma unroll
        for (int dy = 0; dy < 2; dy++) {
            #pragma unroll
            for (int dx = 0; dx < 2; dx++) {
                int xi = x0 + dx;
                int yi = y0 + dy;
                if ((unsigned)xi < (unsigned)WB && (unsigned)yi < (unsigned)HB) {
                    float wx = dx ? tx : __fsub_rn(1.0f, tx);
                    float wy = dy ? ty : __fsub_rn(1.0f, ty);
                    float wgt = __fmul_rn(wx, wy);
                    float4* p = accum_n + ((size_t)yi << 9) + xi;
                    asm volatile(
                        "red.global.add.v4.f32 [%0], {%1, %2, %3, %4};"
                        :: "l"(p), "f"(__fmul_rn(vr, wgt)), "f"(__fmul_rn(vg, wgt)),
                           "f"(__fmul_rn(vb, wgt)), "f"(__fmul_rn(wt, wgt))
                        : "memory");
                }
            }
        }
    }
}

// One image row per block (128 threads x 4 px). No div/mod, no local arrays,
// one rcp per pixel (output-direct division: approx rounding is fine).
__global__ __launch_bounds__(128) void finalize_kernel(float* __restrict__ out) {
    int nh = blockIdx.x;              // n*512 + h
    int h  = nh & (HB - 1);
    int n  = nh >> 9;
    int w4 = threadIdx.x << 2;        // 0..508

    const float4* src = g_accum + (((size_t)n << 9) + (HB - 1 - h)) * WB + w4;
    float4 a0 = src[0], a1 = src[1], a2 = src[2], a3 = src[3];

    float w0 = a0.w, w1 = a1.w, w2 = a2.w, w3 = a3.w;
    float r0 = __frcp_rn(fmaxf(w0, 1e-8f));
    float r1 = __frcp_rn(fmaxf(w1, 1e-8f));
    float r2 = __frcp_rn(fmaxf(w2, 1e-8f));
    float r3 = __frcp_rn(fmaxf(w3, 1e-8f));

    size_t base = ((size_t)nh << 9) + w4;         // output pixel index
    float4* otex = (float4*)(out + base * 3);
    float4* otw  = (float4*)(out + (size_t)NPIX * 3 + base * 3);

    otex[0] = make_float4(a0.x * r0, a0.y * r0, a0.z * r0, a1.x * r1);
    otex[1] = make_float4(a1.y * r1, a1.z * r1, a2.x * r2, a2.y * r2);
    otex[2] = make_float4(a2.z * r2, a3.x * r3, a3.y * r3, a3.z * r3);

    otw[0] = make_float4(w0, w0, w0, w1);
    otw[1] = make_float4(w1, w1, w2, w2);
    otw[2] = make_float4(w2, w3, w3, w3);
}

extern "C" void kernel_launch(void* const* d_in, const int* in_sizes, int n_in,
                              void* d_out, int out_size) {
    const int*   p2f    = (const int*)  d_in[0];
    const float* bary   = (const float*)d_in[1];
    const float* dists  = (const float*)d_in[2];
    const float* zbuf   = (const float*)d_in[3];
    const float* images = (const float*)d_in[4];
    const float* fuv    = (const float*)d_in[5];
    float* out = (float*)d_out;

    // Zero the accumulator via a memset node (graph-capturable, no alloc).
    void* accum_ptr = nullptr;
    cudaGetSymbolAddress(&accum_ptr, g_accum);
    cudaMemsetAsync(accum_ptr, 0, (size_t)NPIX * sizeof(float4), 0);

    splat_kernel<<<NPIX / 256, 256>>>(p2f, bary, dists, zbuf, images, fuv);
    finalize_kernel<<<NB * HB, 128>>>(out);
}

// round 5
// speedup vs baseline: 1.0326x; 1.0326x over previous
#include <cuda_runtime.h>
#include <math.h>

// Problem constants (fixed shapes)
#define NB 4
#define HB 512
#define WB 512
#define NPIX (NB * HB * WB)   // 1,048,576 pixels

#define SIGMA_F 1e-4f
#define GAMMA_F 1e-4f
// DELTA = exp(1e-10/1e-4)*1e-10 computed in float64 -> float32
#define DELTA_F 1.0000010000005e-10f

// Accumulator: per (n, y, x) -> {sum r*w, sum g*w, sum b*w, sum w} (16 MB).
// Zero-initialized at module load; finalize_kernel re-zeros it each call,
// so no memset launch is ever needed.
__device__ float4 g_accum[NB * HB * WB];

__global__ __launch_bounds__(256) void splat_kernel(
    const int*   __restrict__ p2f,     // [N,H,W,K]
    const float* __restrict__ bary,    // [N,H,W,K,3]
    const float* __restrict__ dists,   // [N,H,W,K]
    const float* __restrict__ zbuf,    // [N,H,W,K]
    const float* __restrict__ images,  // [N,H,W,C]
    const float* __restrict__ fuv)     // [F,3,2]
{
    int idx = blockIdx.x * blockDim.x + threadIdx.x;
    int w = idx & (WB - 1);
    int h = (idx >> 9) & (HB - 1);
    int n = idx >> 18;

    // Front-batched vectorized loads (max MLP; K=4 innermost, 16B aligned).
    int4   f4 = __ldg(((const int4*)p2f) + idx);
    float4 z4 = __ldg(((const float4*)zbuf) + idx);
    float4 d4 = __ldg(((const float4*)dists) + idx);
    const float4* bq = ((const float4*)bary) + (size_t)idx * 3;
    float4 q0 = __ldg(bq + 0);
    float4 q1 = __ldg(bq + 1);
    float4 q2 = __ldg(bq + 2);
    float r = __ldg(images + (size_t)idx * 3 + 0);
    float g = __ldg(images + (size_t)idx * 3 + 1);
    float b = __ldg(images + (size_t)idx * 3 + 2);

    int   fk[4] = {f4.x, f4.y, f4.z, f4.w};
    float dk[4] = {d4.x, d4.y, d4.z, d4.w};
    float zk[4] = {z4.x, z4.y, z4.z, z4.w};
    float bc[12] = {q0.x, q0.y, q0.z, q0.w, q1.x, q1.y, q1.z, q1.w,
                    q2.x, q2.y, q2.z, q2.w};

    // ---- Candidate selection on CHEAP approximate z_inv ----
    // exp((z_inv - z_max)/GAMMA) is bitwise 0 whenever z_inv - z_max <
    // -0.0105 (arg < -104.9 < log(min_subnormal/2)). Approximate z_inv errs
    // <= ~2.4e-7 << window slack -> candidates provably cover all nonzero
    // exps; excluded k have wnum == 0 exactly.
    const float R99 = 1.0f / 99.0f;
    float zA[4];
    bool  m[4];
    float maxA = -1e30f;
    #pragma unroll
    for (int k = 0; k < 4; k++) {
        m[k] = (fk[k] >= 0);
        zA[k] = m[k] ? (100.0f - zk[k]) * R99 : 0.0f;
        maxA = fmaxf(maxA, zA[k]);
    }
    float thresh = maxA - 0.0105f;

    // Exact z_inv (true division; rounding amplified x1e4 by the exp) for
    // candidates only; exact z_max over candidates == exact global max.
    bool  cand[4];
    float ze[4];
    float zmax = -1e30f;
    #pragma unroll
    for (int k = 0; k < 4; k++) {
        cand[k] = m[k] && (zA[k] >= thresh);
        ze[k] = cand[k] ? __fdiv_rn(__fsub_rn(100.0f, zk[k]), 99.0f) : -1e30f;
        zmax = fmaxf(zmax, ze[k]);
    }

    // wnum: heavy exp/sigmoid path only where it can be nonzero (~1/pixel).
    float wnum[4];
    float s = 0.0f;
    #pragma unroll
    for (int k = 0; k < 4; k++) {
        float wv = 0.0f;
        if (cand[k]) {
            float earg = __fdiv_rn(__fsub_rn(ze[k], zmax), GAMMA_F);
            float e = expf(earg);          // argmax: earg==0 -> e==1 exactly
            if (e != 0.0f) {
                float sarg = __fdiv_rn(-dk[k], SIGMA_F);
                float pr = __fdiv_rn(1.0f, __fadd_rn(1.0f, expf(-sarg)));
                wv = __fmul_rn(pr, e);
            }
        }
        wnum[k] = wv;
        s = __fadd_rn(s, wv);
    }
    float denom = __fadd_rn(s, DELTA_F);

    // linspace(0, 512, 512)[i] = i * (512/511)
    const float STEP = 512.0f / 511.0f;
    float linx = __fmul_rn((float)w, STEP);
    float liny = __fmul_rn((float)h, STEP);

    float4* accum_n = g_accum + ((size_t)n << 18);

    #pragma unroll
    for (int k = 0; k < 4; k++) {
        if (wnum[k] == 0.0f) continue;   // scatter of zeros == bitwise no-op
        float wt = __fdiv_rn(wnum[k], denom);

        // Gather face UVs as 3x float2 (24B stride, 8B aligned) and blend.
        // Strict mul/add (no FMA) to match XLA: floor() bin is ulp-sensitive.
        const float2* uvp = (const float2*)(fuv + (size_t)fk[k] * 6);
        float2 u0 = __ldg(uvp + 0);
        float2 u1 = __ldg(uvp + 1);
        float2 u2 = __ldg(uvp + 2);
        float b0 = bc[k * 3 + 0], b1 = bc[k * 3 + 1], b2 = bc[k * 3 + 2];
        float ux = __fadd_rn(__fadd_rn(__fmul_rn(b0, u0.x),
                                       __fmul_rn(b1, u1.x)),
                             __fmul_rn(b2, u2.x));
        float uy = __fadd_rn(__fadd_rn(__fmul_rn(b0, u0.y),
                                       __fmul_rn(b1, u1.y)),
                             __fmul_rn(b2, u2.y));

        float gx = __fadd_rn(__fmul_rn(ux, 2.0f), -1.0f);
        float gy = __fadd_rn(__fmul_rn(uy, 2.0f), -1.0f);
        float tgx = __fmul_rn(__fadd_rn(__fmul_rn(gx, 0.5f), 0.5f), 512.0f);
        float tgy = __fmul_rn(__fadd_rn(__fmul_rn(gy, 0.5f), 0.5f), 512.0f);

        float fx = __fadd_rn(__fsub_rn(tgx, linx), (float)w);
        float fy = __fadd_rn(__fsub_rn(tgy, liny), (float)h);

        float x0f = floorf(fx), y0f = floorf(fy);
        int x0 = (int)x0f, y0 = (int)y0f;
        float tx = __fsub_rn(fx, x0f), ty = __fsub_rn(fy, y0f);

        float vr = __fmul_rn(r, wt), vg = __fmul_rn(g, wt), vb = __fmul_rn(b, wt);

        #pragma unroll
        for (int dy = 0; dy < 2; dy++) {
            #pragma unroll
            for (int dx = 0; dx < 2; dx++) {
                int xi = x0 + dx;
                int yi = y0 + dy;
                if ((unsigned)xi < (unsigned)WB && (unsigned)yi < (unsigned)HB) {
                    float wx = dx ? tx : __fsub_rn(1.0f, tx);
                    float wy = dy ? ty : __fsub_rn(1.0f, ty);
                    float wgt = __fmul_rn(wx, wy);
                    float4* p = accum_n + ((size_t)yi << 9) + xi;
                    asm volatile(
                        "red.global.add.v4.f32 [%0], {%1, %2, %3, %4};"
                        :: "l"(p), "f"(__fmul_rn(vr, wgt)), "f"(__fmul_rn(vg, wgt)),
                           "f"(__fmul_rn(vb, wgt)), "f"(__fmul_rn(wt, wgt))
                        : "memory");
                }
            }
        }
    }
}

// 4 consecutive pixels per thread. Reads the accumulator, writes zeros back
// (leaving it ready for the next call), normalizes, flips H, emits both
// outputs with float4 stores. One rcp per pixel (output-direct division).
__global__ __launch_bounds__(256) void finalize_kernel(float* __restrict__ out) {
    int t = blockIdx.x * blockDim.x + threadIdx.x;   // [0, NPIX/4)
    int base = t << 2;
    int w = base & (WB - 1);           // multiple of 4, same row
    int h = (base >> 9) & (HB - 1);
    int n = base >> 18;

    float4* src = g_accum + (((size_t)n << 9) + (HB - 1 - h)) * WB + w;
    float4 a0 = src[0], a1 = src[1], a2 = src[2], a3 = src[3];
    const float4 zz = make_float4(0.f, 0.f, 0.f, 0.f);
    src[0] = zz; src[1] = zz; src[2] = zz; src[3] = zz;

    float w0 = a0.w, w1 = a1.w, w2 = a2.w, w3 = a3.w;
    float r0 = __frcp_rn(fmaxf(w0, 1e-8f));
    float r1 = __frcp_rn(fmaxf(w1, 1e-8f));
    float r2 = __frcp_rn(fmaxf(w2, 1e-8f));
    float r3 = __frcp_rn(fmaxf(w3, 1e-8f));

    float4* otex = (float4*)(out + (size_t)base * 3);
    float4* otw  = (float4*)(out + (size_t)NPIX * 3 + (size_t)base * 3);

    otex[0] = make_float4(a0.x * r0, a0.y * r0, a0.z * r0, a1.x * r1);
    otex[1] = make_float4(a1.y * r1, a1.z * r1, a2.x * r2, a2.y * r2);
    otex[2] = make_float4(a2.z * r2, a3.x * r3, a3.y * r3, a3.z * r3);

    otw[0] = make_float4(w0, w0, w0, w1);
    otw[1] = make_float4(w1, w1, w2, w2);
    otw[2] = make_float4(w2, w3, w3, w3);
}

extern "C" void kernel_launch(void* const* d_in, const int* in_sizes, int n_in,
                              void* d_out, int out_size) {
    const int*   p2f    = (const int*)  d_in[0];
    const float* bary   = (const float*)d_in[1];
    const float* dists  = (const float*)d_in[2];
    const float* zbuf   = (const float*)d_in[3];
    const float* images = (const float*)d_in[4];
    const float* fuv    = (const float*)d_in[5];
    float* out = (float*)d_out;

    splat_kernel<<<NPIX / 256, 256>>>(p2f, bary, dists, zbuf, images, fuv);
    finalize_kernel<<<NPIX / 1024, 256>>>(out);
}

// round 6
// speedup vs baseline: 1.1893x; 1.1518x over previous
#include <cuda_runtime.h>
#include <math.h>

// Problem constants (fixed shapes)
#define NB 4
#define HB 512
#define WB 512
#define NPIX (NB * HB * WB)   // 1,048,576 pixels

#define SIGMA_F 1e-4f
#define GAMMA_F 1e-4f
// DELTA = exp(1e-10/1e-4)*1e-10 computed in float64 -> float32
#define DELTA_F 1.0000010000005e-10f

// Accumulator: per (n, y, x) -> {sum r*w, sum g*w, sum b*w, sum w} (16 MB).
__device__ float4 g_accum[NB * HB * WB];

__global__ __launch_bounds__(256) void splat_kernel(
    const int*   __restrict__ p2f,     // [N,H,W,K]
    const float* __restrict__ bary,    // [N,H,W,K,3]
    const float* __restrict__ dists,   // [N,H,W,K]
    const float* __restrict__ zbuf,    // [N,H,W,K]
    const float* __restrict__ images,  // [N,H,W,C]
    const float* __restrict__ fuv)     // [F,3,2]
{
    int idx = blockIdx.x * blockDim.x + threadIdx.x;
    int w = idx & (WB - 1);
    int h = (idx >> 9) & (HB - 1);
    int n = idx >> 18;

    // Front-batched vectorized loads (max MLP; K=4 innermost, 16B aligned).
    int4   f4 = __ldg(((const int4*)p2f) + idx);
    float4 z4 = __ldg(((const float4*)zbuf) + idx);
    float4 d4 = __ldg(((const float4*)dists) + idx);
    const float4* bq = ((const float4*)bary) + (size_t)idx * 3;
    float4 q0 = __ldg(bq + 0);
    float4 q1 = __ldg(bq + 1);
    float4 q2 = __ldg(bq + 2);
    float r = __ldg(images + (size_t)idx * 3 + 0);
    float g = __ldg(images + (size_t)idx * 3 + 1);
    float b = __ldg(images + (size_t)idx * 3 + 2);

    int   fk[4] = {f4.x, f4.y, f4.z, f4.w};
    float dk[4] = {d4.x, d4.y, d4.z, d4.w};
    float zk[4] = {z4.x, z4.y, z4.z, z4.w};
    float bc[12] = {q0.x, q0.y, q0.z, q0.w, q1.x, q1.y, q1.z, q1.w,
                    q2.x, q2.y, q2.z, q2.w};

    // ---- Candidate selection on CHEAP approximate z_inv ----
    // exp((z_inv - z_max)/GAMMA) is bitwise 0 whenever z_inv - z_max <
    // -0.0105 (arg < -104.9 < log(min_subnormal/2)). Approximate z_inv errs
    // <= ~2.4e-7 << window slack -> candidates provably cover all nonzero
    // exps; excluded k have wnum == 0 exactly.
    const float R99 = 1.0f / 99.0f;
    float zA[4];
    bool  m[4];
    float maxA = -1e30f;
    #pragma unroll
    for (int k = 0; k < 4; k++) {
        m[k] = (fk[k] >= 0);
        zA[k] = m[k] ? (100.0f - zk[k]) * R99 : 0.0f;
        maxA = fmaxf(maxA, zA[k]);
    }
    float thresh = maxA - 0.0105f;

    // Exact z_inv (true division; rounding amplified x1e4 by the exp) for
    // candidates only; exact z_max over candidates == exact global max.
    bool  cand[4];
    float ze[4];
    float zmax = -1e30f;
    #pragma unroll
    for (int k = 0; k < 4; k++) {
        cand[k] = m[k] && (zA[k] >= thresh);
        ze[k] = cand[k] ? __fdiv_rn(__fsub_rn(100.0f, zk[k]), 99.0f) : -1e30f;
        zmax = fmaxf(zmax, ze[k]);
    }

    // wnum: heavy exp/sigmoid path only where it can be nonzero (~1/pixel).
    float wnum[4];
    float s = 0.0f;
    #pragma unroll
    for (int k = 0; k < 4; k++) {
        float wv = 0.0f;
        if (cand[k]) {
            float earg = __fdiv_rn(__fsub_rn(ze[k], zmax), GAMMA_F);
            float e = expf(earg);          // argmax: earg==0 -> e==1 exactly
            if (e != 0.0f) {
                float sarg = __fdiv_rn(-dk[k], SIGMA_F);
                float pr = __fdiv_rn(1.0f, __fadd_rn(1.0f, expf(-sarg)));
                wv = __fmul_rn(pr, e);
            }
        }
        wnum[k] = wv;
        s = __fadd_rn(s, wv);
    }
    float denom = __fadd_rn(s, DELTA_F);

    // linspace(0, 512, 512)[i] = i * (512/511)
    const float STEP = 512.0f / 511.0f;
    float linx = __fmul_rn((float)w, STEP);
    float liny = __fmul_rn((float)h, STEP);

    float4* accum_n = g_accum + ((size_t)n << 18);

    #pragma unroll
    for (int k = 0; k < 4; k++) {
        if (wnum[k] == 0.0f) continue;   // scatter of zeros == bitwise no-op
        float wt = __fdiv_rn(wnum[k], denom);

        // Gather face UVs as 3x float2 (24B stride, 8B aligned) and blend.
        // Strict mul/add (no FMA) to match XLA: floor() bin is ulp-sensitive.
        const float2* uvp = (const float2*)(fuv + (size_t)fk[k] * 6);
        float2 u0 = __ldg(uvp + 0);
        float2 u1 = __ldg(uvp + 1);
        float2 u2 = __ldg(uvp + 2);
        float b0 = bc[k * 3 + 0], b1 = bc[k * 3 + 1], b2 = bc[k * 3 + 2];
        float ux = __fadd_rn(__fadd_rn(__fmul_rn(b0, u0.x),
                                       __fmul_rn(b1, u1.x)),
                             __fmul_rn(b2, u2.x));
        float uy = __fadd_rn(__fadd_rn(__fmul_rn(b0, u0.y),
                                       __fmul_rn(b1, u1.y)),
                             __fmul_rn(b2, u2.y));

        float gx = __fadd_rn(__fmul_rn(ux, 2.0f), -1.0f);
        float gy = __fadd_rn(__fmul_rn(uy, 2.0f), -1.0f);
        float tgx = __fmul_rn(__fadd_rn(__fmul_rn(gx, 0.5f), 0.5f), 512.0f);
        float tgy = __fmul_rn(__fadd_rn(__fmul_rn(gy, 0.5f), 0.5f), 512.0f);

        float fx = __fadd_rn(__fsub_rn(tgx, linx), (float)w);
        float fy = __fadd_rn(__fsub_rn(tgy, liny), (float)h);

        float x0f = floorf(fx), y0f = floorf(fy);
        int x0 = (int)x0f, y0 = (int)y0f;
        float tx = __fsub_rn(fx, x0f), ty = __fsub_rn(fy, y0f);

        float vr = __fmul_rn(r, wt), vg = __fmul_rn(g, wt), vb = __fmul_rn(b, wt);

        #pragma unroll
        for (int dy = 0; dy < 2; dy++) {
            #pragma unroll
            for (int dx = 0; dx < 2; dx++) {
                int xi = x0 + dx;
                int yi = y0 + dy;
                if ((unsigned)xi < (unsigned)WB && (unsigned)yi < (unsigned)HB) {
                    float wx = dx ? tx : __fsub_rn(1.0f, tx);
                    float wy = dy ? ty : __fsub_rn(1.0f, ty);
                    float wgt = __fmul_rn(wx, wy);
                    float4* p = accum_n + ((size_t)yi << 9) + xi;
                    asm volatile(
                        "red.global.add.v4.f32 [%0], {%1, %2, %3, %4};"
                        :: "l"(p), "f"(__fmul_rn(vr, wgt)), "f"(__fmul_rn(vg, wgt)),
                           "f"(__fmul_rn(vb, wgt)), "f"(__fmul_rn(wt, wgt))
                        : "memory");
                }
            }
        }
    }
}

// One pixel per thread. Accumulator load is fully coalesced (lane i -> the
// i-th consecutive float4: 512B/warp = 4 lines per LDG.128 instead of the
// 16 wavefronts the 4-px strided variant paid). Outputs are 6 scalar STG.32
// per thread — contiguous across the warp, fire-and-forget.
__global__ __launch_bounds__(256) void finalize_kernel(float* __restrict__ out) {
    int idx = blockIdx.x * blockDim.x + threadIdx.x;   // output pixel
    int w = idx & (WB - 1);
    int h = (idx >> 9) & (HB - 1);
    int n = idx >> 18;

    // Flip H: output row h reads accumulator row (H-1-h); same w order.
    float4 a = __ldg(&g_accum[(((size_t)n << 9) + (HB - 1 - h)) * WB + w]);
    float wsum = a.w;
    float rc = __frcp_rn(fmaxf(wsum, 1e-8f));

    float* tex = out + (size_t)idx * 3;
    tex[0] = a.x * rc;
    tex[1] = a.y * rc;
    tex[2] = a.z * rc;

    float* tw = out + (size_t)NPIX * 3 + (size_t)idx * 3;
    tw[0] = wsum;
    tw[1] = wsum;
    tw[2] = wsum;
}

extern "C" void kernel_launch(void* const* d_in, const int* in_sizes, int n_in,
                              void* d_out, int out_size) {
    const int*   p2f    = (const int*)  d_in[0];
    const float* bary   = (const float*)d_in[1];
    const float* dists  = (const float*)d_in[2];
    const float* zbuf   = (const float*)d_in[3];
    const float* images = (const float*)d_in[4];
    const float* fuv    = (const float*)d_in[5];
    float* out = (float*)d_out;

    // Zero the accumulator via a memset node (graph-capturable, no alloc).
    void* accum_ptr = nullptr;
    cudaGetSymbolAddress(&accum_ptr, g_accum);
    cudaMemsetAsync(accum_ptr, 0, (size_t)NPIX * sizeof(float4), 0);

    splat_kernel<<<NPIX / 256, 256>>>(p2f, bary, dists, zbuf, images, fuv);
    finalize_kernel<<<NPIX / 256, 256>>>(out);
}

// round 7
// speedup vs baseline: 1.1900x; 1.0006x over previous
#include <cuda_runtime.h>
#include <math.h>

// Problem constants (fixed shapes)
#define NB 4
#define HB 512
#define WB 512
#define NPIX (NB * HB * WB)   // 1,048,576 pixels

#define SIGMA_F 1e-4f
#define GAMMA_F 1e-4f
// DELTA = exp(1e-10/1e-4)*1e-10 computed in float64 -> float32
#define DELTA_F 1.0000010000005e-10f

// Accumulator: per (n, y, x) -> {sum r*w, sum g*w, sum b*w, sum w} (16 MB).
__device__ float4 g_accum[NB * HB * WB];

// One (pixel, k) pair per lane: lanes 4i..4i+3 hold k=0..3 of pixel i.
// Quad-wide shuffles implement the K-reduction (z_max, sum of wnum).
__global__ __launch_bounds__(256) void splat_kernel(
    const int*   __restrict__ p2f,     // [N,H,W,K]
    const float* __restrict__ bary,    // [N,H,W,K,3]
    const float* __restrict__ dists,   // [N,H,W,K]
    const float* __restrict__ zbuf,    // [N,H,W,K]
    const float* __restrict__ images,  // [N,H,W,C]
    const float* __restrict__ fuv)     // [F,3,2]
{
    int t = blockIdx.x * blockDim.x + threadIdx.x;   // [0, 4*NPIX), exact grid
    int idx = t >> 2;                                // pixel
    int w = idx & (WB - 1);
    int h = (idx >> 9) & (HB - 1);
    int n = idx >> 18;

    // Coalesced per-lane loads (front-batched for MLP).
    int   fk = __ldg(p2f + t);
    float zk = __ldg(zbuf + t);
    float dk = __ldg(dists + t);
    const float* bp = bary + (size_t)t * 3;
    float b0 = __ldg(bp + 0);
    float b1 = __ldg(bp + 1);
    float b2 = __ldg(bp + 2);
    // RGB: all 4 lanes of a quad read the same 12B (L1 broadcast).
    float r = __ldg(images + (size_t)idx * 3 + 0);
    float g = __ldg(images + (size_t)idx * 3 + 1);
    float b = __ldg(images + (size_t)idx * 3 + 2);

    // ---- Candidate selection on CHEAP approximate z_inv ----
    // exp((z_inv - z_max)/GAMMA) is bitwise 0 whenever z_inv - z_max <
    // -0.0105 (arg < -104.9 < log(min_subnormal/2)). Approximate z_inv errs
    // <= ~2.4e-7 << window slack -> candidates provably cover all nonzero
    // exps; excluded k have wnum == 0 exactly.
    const float R99 = 1.0f / 99.0f;
    bool  m  = (fk >= 0);
    float zA = m ? (100.0f - zk) * R99 : 0.0f;
    float maxA = zA;
    maxA = fmaxf(maxA, __shfl_xor_sync(0xffffffffu, maxA, 1));
    maxA = fmaxf(maxA, __shfl_xor_sync(0xffffffffu, maxA, 2));
    bool cand = m && (zA >= maxA - 0.0105f);

    // Predicated UV gather for candidates (~26% of lanes): issued early so
    // the gather latency overlaps the exp/div weight chain below.
    float2 u0, u1, u2;
    if (cand) {
        const float2* uvp = (const float2*)(fuv + (size_t)fk * 6);
        u0 = __ldg(uvp + 0);
        u1 = __ldg(uvp + 1);
        u2 = __ldg(uvp + 2);
    }

    // Exact z_inv (true division; rounding amplified x1e4 by the exp) for
    // candidates only; exact max over candidates == exact global max.
    float ze = cand ? __fdiv_rn(__fsub_rn(100.0f, zk), 99.0f) : -1e30f;
    float zmax = ze;
    zmax = fmaxf(zmax, __shfl_xor_sync(0xffffffffu, zmax, 1));
    zmax = fmaxf(zmax, __shfl_xor_sync(0xffffffffu, zmax, 2));

    // wnum: heavy exp/sigmoid path only where it can be nonzero.
    float wv = 0.0f;
    if (cand) {
        float earg = __fdiv_rn(__fsub_rn(ze, zmax), GAMMA_F);
        float e = expf(earg);              // argmax lane: earg==0 -> e==1
        if (e != 0.0f) {
            float sarg = __fdiv_rn(-dk, SIGMA_F);
            float pr = __fdiv_rn(1.0f, __fadd_rn(1.0f, expf(-sarg)));
            wv = __fmul_rn(pr, e);
        }
    }
    // Quad sum (butterfly order: <=1 ulp vs sequential; not exp-amplified).
    float s = wv;
    s = __fadd_rn(s, __shfl_xor_sync(0xffffffffu, s, 1));
    s = __fadd_rn(s, __shfl_xor_sync(0xffffffffu, s, 2));
    float denom = __fadd_rn(s, DELTA_F);

    if (wv == 0.0f) return;                // scatter of zeros == bitwise no-op
    float wt = __fdiv_rn(wv, denom);

    // Barycentric-blend UVs. Strict mul/add (no FMA) to match XLA: the
    // floor() bin below is last-ulp sensitive.
    float ux = __fadd_rn(__fadd_rn(__fmul_rn(b0, u0.x), __fmul_rn(b1, u1.x)),
                         __fmul_rn(b2, u2.x));
    float uy = __fadd_rn(__fadd_rn(__fmul_rn(b0, u0.y), __fmul_rn(b1, u1.y)),
                         __fmul_rn(b2, u2.y));

    float gx = __fadd_rn(__fmul_rn(ux, 2.0f), -1.0f);
    float gy = __fadd_rn(__fmul_rn(uy, 2.0f), -1.0f);
    float tgx = __fmul_rn(__fadd_rn(__fmul_rn(gx, 0.5f), 0.5f), 512.0f);
    float tgy = __fmul_rn(__fadd_rn(__fmul_rn(gy, 0.5f), 0.5f), 512.0f);

    // linspace(0, 512, 512)[i] = i * (512/511); fx = (target - lin) + coord
    const float STEP = 512.0f / 511.0f;
    float fx = __fadd_rn(__fsub_rn(tgx, __fmul_rn((float)w, STEP)), (float)w);
    float fy = __fadd_rn(__fsub_rn(tgy, __fmul_rn((float)h, STEP)), (float)h);

    float x0f = floorf(fx), y0f = floorf(fy);
    int x0 = (int)x0f, y0 = (int)y0f;
    float tx = __fsub_rn(fx, x0f), ty = __fsub_rn(fy, y0f);

    float vr = __fmul_rn(r, wt), vg = __fmul_rn(g, wt), vb = __fmul_rn(b, wt);
    float4* accum_n = g_accum + ((size_t)n << 18);

    #pragma unroll
    for (int dy = 0; dy < 2; dy++) {
        #pragma unroll
        for (int dx = 0; dx < 2; dx++) {
            int xi = x0 + dx;
            int yi = y0 + dy;
            if ((unsigned)xi < (unsigned)WB && (unsigned)yi < (unsigned)HB) {
                float wx = dx ? tx : __fsub_rn(1.0f, tx);
                float wy = dy ? ty : __fsub_rn(1.0f, ty);
                float wgt = __fmul_rn(wx, wy);
                float4* p = accum_n + ((size_t)yi << 9) + xi;
                asm volatile(
                    "red.global.add.v4.f32 [%0], {%1, %2, %3, %4};"
                    :: "l"(p), "f"(__fmul_rn(vr, wgt)), "f"(__fmul_rn(vg, wgt)),
                       "f"(__fmul_rn(vb, wgt)), "f"(__fmul_rn(wt, wgt))
                    : "memory");
            }
        }
    }
}

// One pixel per thread; coalesced accumulator read, rcp, scalar stores.
__global__ __launch_bounds__(256) void finalize_kernel(float* __restrict__ out) {
    int idx = blockIdx.x * blockDim.x + threadIdx.x;   // output pixel
    int w = idx & (WB - 1);
    int h = (idx >> 9) & (HB - 1);
    int n = idx >> 18;

    // Flip H: output row h reads accumulator row (H-1-h); same w order.
    float4 a = __ldg(&g_accum[(((size_t)n << 9) + (HB - 1 - h)) * WB + w]);
    float wsum = a.w;
    float rc = __frcp_rn(fmaxf(wsum, 1e-8f));

    float* tex = out + (size_t)idx * 3;
    tex[0] = a.x * rc;
    tex[1] = a.y * rc;
    tex[2] = a.z * rc;

    float* tw = out + (size_t)NPIX * 3 + (size_t)idx * 3;
    tw[0] = wsum;
    tw[1] = wsum;
    tw[2] = wsum;
}

extern "C" void kernel_launch(void* const* d_in, const int* in_sizes, int n_in,
                              void* d_out, int out_size) {
    const int*   p2f    = (const int*)  d_in[0];
    const float* bary   = (const float*)d_in[1];
    const float* dists  = (const float*)d_in[2];
    const float* zbuf   = (const float*)d_in[3];
    const float* images = (const float*)d_in[4];
    const float* fuv    = (const float*)d_in[5];
    float* out = (float*)d_out;

    // Zero the accumulator via a memset node (graph-capturable, no alloc).
    void* accum_ptr = nullptr;
    cudaGetSymbolAddress(&accum_ptr, g_accum);
    cudaMemsetAsync(accum_ptr, 0, (size_t)NPIX * sizeof(float4), 0);

    splat_kernel<<<(NPIX * 4) / 256, 256>>>(p2f, bary, dists, zbuf, images, fuv);
    finalize_kernel<<<NPIX / 256, 256>>>(out);
}